// round 4
// baseline (speedup 1.0000x reference)
#include <cuda_runtime.h>
#include <math.h>
#include <stdint.h>

#define NPTS 16384
#define MCTR 4096
#define NIN  64
#define NOUTF 128
#define DIMF 67
#define KNB  64
#define R2   0.25f

#define OFF_POS   (MCTR * NOUTF)
#define OFF_BATCH (OFF_POS + MCTR * 3)
#define OFF_IDX   (OFF_BATCH + MCTR)

#define SFAC 0.9999950000374996f

__device__ int g_idx[MCTR];
__device__ int g_nbr[MCTR * KNB];
__device__ int g_cnt[MCTR];
__device__ int g_sortidx[NPTS];

// ---------------- helpers -----------------------------------------------------

__device__ __forceinline__ uint32_t smem_u32(const void* p) {
    uint32_t a;
    asm("{ .reg .u64 t; cvta.to.shared.u64 t, %1; cvt.u32.u64 %0, t; }"
        : "=r"(a) : "l"(p));
    return a;
}
__device__ __forceinline__ uint32_t ctarank() {
    uint32_t r;
    asm("mov.u32 %0, %%cluster_ctarank;" : "=r"(r));
    return r;
}
__device__ __forceinline__ void st_cluster_u64(uint32_t local_addr, uint32_t rank,
                                               unsigned long long v) {
    asm volatile(
        "{ .reg .u32 ra; mapa.shared::cluster.u32 ra, %0, %1; "
        "st.shared::cluster.u64 [ra], %2; }"
        :: "r"(local_addr), "r"(rank), "l"(v) : "memory");
}
__device__ __forceinline__ void mbar_arrive_cluster(uint32_t local_mbar, uint32_t rank) {
    asm volatile(
        "{ .reg .u32 ra; mapa.shared::cluster.u32 ra, %0, %1; "
        "mbarrier.arrive.release.cluster.shared::cluster.b64 _, [ra]; }"
        :: "r"(local_mbar), "r"(rank) : "memory");
}
__device__ __forceinline__ void mbar_wait_cluster(uint32_t mbar, uint32_t parity) {
    asm volatile(
        "{\n\t"
        ".reg .pred P;\n\t"
        "W_%=:\n\t"
        "mbarrier.try_wait.parity.acquire.cluster.shared::cta.b64 P, [%0], %1, 0x989680;\n\t"
        "@P bra.uni D_%=;\n\t"
        "bra.uni W_%=;\n\t"
        "D_%=:\n\t"
        "}"
        :: "r"(mbar), "r"(parity) : "memory");
}
__device__ __forceinline__ unsigned redux_max_u32(unsigned v) {
    unsigned r;
    asm volatile("redux.sync.max.u32 %0, %1, 0xffffffff;" : "=r"(r) : "r"(v));
    return r;
}
// warp argmax over (valbits, lo=~origidx): returns in all lanes
__device__ __forceinline__ void warp_argmax2(unsigned& v, unsigned& lo) {
    unsigned m  = redux_max_u32(v);
    unsigned cl = (v == m) ? lo : 0u;
    lo = redux_max_u32(cl);
    v  = m;
}

// ---------------- morton sort: single CTA bitonic -----------------------------

__device__ __forceinline__ unsigned expand_bits10(unsigned x) {
    x &= 0x3ffu;
    x = (x | (x << 16)) & 0x030000FFu;
    x = (x | (x << 8))  & 0x0300F00Fu;
    x = (x | (x << 4))  & 0x030C30C3u;
    x = (x | (x << 2))  & 0x09249249u;
    return x;
}

__global__ void __launch_bounds__(1024, 1) sort_kernel(const float* __restrict__ pos)
{
    extern __shared__ unsigned long long keys[];   // [NPTS]
    const int t = threadIdx.x;

    for (int i = t; i < NPTS; i += 1024) {
        float x = pos[3 * i + 0], y = pos[3 * i + 1], z = pos[3 * i + 2];
        unsigned qx = (unsigned)min(1023, max(0, (int)((x + 8.0f) * 64.0f)));
        unsigned qy = (unsigned)min(1023, max(0, (int)((y + 8.0f) * 64.0f)));
        unsigned qz = (unsigned)min(1023, max(0, (int)((z + 8.0f) * 64.0f)));
        unsigned mo = expand_bits10(qx) | (expand_bits10(qy) << 1) | (expand_bits10(qz) << 2);
        keys[i] = ((unsigned long long)mo << 32) | (unsigned)i;
    }
    __syncthreads();

    for (int k = 2; k <= NPTS; k <<= 1) {
        for (int j = k >> 1; j > 0; j >>= 1) {
            for (int i = t; i < NPTS; i += 1024) {
                int l = i ^ j;
                if (l > i) {
                    unsigned long long a = keys[i], b = keys[l];
                    bool up = ((i & k) == 0);
                    if ((a > b) == up) { keys[i] = b; keys[l] = a; }
                }
            }
            __syncthreads();
        }
    }
    for (int i = t; i < NPTS; i += 1024)
        g_sortidx[i] = (int)(keys[i] & 0xFFFFFFFFull);
}

// ---------------- FPS: 8-CTA cluster + group pruning --------------------------
// 128 groups of 128 Morton-contiguous points; group g -> CTA (g & 7), warp (g>>3).
// Skip a group when (dist(c_new, gcenter) - grad)^2 >= 1.01 * group_max_dmin.
// All reductions on (dminBits, ~origIdx): u64-max == jnp.argmax first-max.

#define FPS_CTAS 8
#define FPS_THREADS 512
#define FPS_WARPS 16
#define PPT 4

__global__ void __launch_bounds__(FPS_THREADS, 1) __cluster_dims__(FPS_CTAS, 1, 1)
fps_cluster_kernel(const float* __restrict__ pos)
{
    extern __shared__ float sm[];
    float* sx = sm;
    float* sy = sx + NPTS;
    float* sz = sy + NPTS;
    __shared__ unsigned long long s_slot[2][FPS_CTAS];
    __shared__ unsigned long long s_wkey[FPS_WARPS];
    __shared__ unsigned long long s_gkey[FPS_WARPS];
    __shared__ float4 s_gmeta[FPS_WARPS];
    __shared__ unsigned long long s_mbar;

    const int t    = threadIdx.x;
    const int lane = t & 31;
    const int wid  = t >> 5;
    const uint32_t rank = ctarank();
    const int grp  = wid * FPS_CTAS + (int)rank;       // interleaved assignment
    const int slot0 = grp * 128 + lane * PPT;

    for (int i = t; i < NPTS; i += FPS_THREADS) {
        sx[i] = pos[3 * i + 0];
        sy[i] = pos[3 * i + 1];
        sz[i] = pos[3 * i + 2];
    }
    const uint32_t mbar  = smem_u32(&s_mbar);
    const uint32_t sl0   = smem_u32(&s_slot[0][0]);
    if (t == 0)
        asm volatile("mbarrier.init.shared.b64 [%0], %1;"
                     :: "r"(mbar), "r"(FPS_CTAS) : "memory");
    __syncthreads();

    // my 4 sorted points (registers), original indices
    const float INF = __int_as_float(0x7f800000);
    int   oidx[PPT];
    float px[PPT], py[PPT], pz[PPT], dmin[PPT];
#pragma unroll
    for (int k = 0; k < PPT; k++) {
        int o   = g_sortidx[slot0 + k];
        oidx[k] = o;
        px[k] = sx[o]; py[k] = sy[o]; pz[k] = sz[o];
        dmin[k] = INF;
    }

    // group bounds: bbox center + max radius (inflated)
    float mnx = px[0], mxx = px[0], mny = py[0], mxy = py[0], mnz = pz[0], mxz = pz[0];
#pragma unroll
    for (int k = 1; k < PPT; k++) {
        mnx = fminf(mnx, px[k]); mxx = fmaxf(mxx, px[k]);
        mny = fminf(mny, py[k]); mxy = fmaxf(mxy, py[k]);
        mnz = fminf(mnz, pz[k]); mxz = fmaxf(mxz, pz[k]);
    }
#pragma unroll
    for (int o = 16; o > 0; o >>= 1) {
        mnx = fminf(mnx, __shfl_xor_sync(0xffffffffu, mnx, o));
        mxx = fmaxf(mxx, __shfl_xor_sync(0xffffffffu, mxx, o));
        mny = fminf(mny, __shfl_xor_sync(0xffffffffu, mny, o));
        mxy = fmaxf(mxy, __shfl_xor_sync(0xffffffffu, mxy, o));
        mnz = fminf(mnz, __shfl_xor_sync(0xffffffffu, mnz, o));
        mxz = fmaxf(mxz, __shfl_xor_sync(0xffffffffu, mxz, o));
    }
    float gx = 0.5f * (mnx + mxx), gy = 0.5f * (mny + mxy), gz = 0.5f * (mnz + mxz);
    float r2m = 0.f;
#pragma unroll
    for (int k = 0; k < PPT; k++) {
        float dx = px[k] - gx, dy = py[k] - gy, dz = pz[k] - gz;
        r2m = fmaxf(r2m, dx * dx + dy * dy + dz * dz);
    }
#pragma unroll
    for (int o = 16; o > 0; o >>= 1)
        r2m = fmaxf(r2m, __shfl_xor_sync(0xffffffffu, r2m, o));
    float gr = sqrtf(r2m) * 1.001f + 1e-6f;

    if (lane == 0) {
        s_gmeta[wid] = make_float4(gx, gy, gz, gr);
        unsigned long long k0 = ((unsigned long long)0x7f800000u << 32);
        s_gkey[wid] = k0;
        s_wkey[wid] = k0;
    }
    __syncthreads();
    asm volatile("barrier.cluster.arrive.aligned;" ::: "memory");
    asm volatile("barrier.cluster.wait.aligned;" ::: "memory");

    float cx = sx[0], cy = sy[0], cz = sz[0];
    if (rank == 0 && t == 0) g_idx[0] = 0;

    unsigned par = 0;

    for (int it = 1; it < MCTR; it++) {
        // ---- group skip test (uniform across warp) ----
        float4 meta = s_gmeta[wid];
        unsigned long long gkey = s_gkey[wid];
        float dmaxf = __uint_as_float((unsigned)(gkey >> 32));
        float ddx = cx - meta.x, ddy = cy - meta.y, ddz = cz - meta.z;
        float dc  = sqrtf(ddx * ddx + ddy * ddy + ddz * ddz);
        float s   = dc - meta.w;
        bool skip = (s > 0.f) && (s * s >= dmaxf * 1.01f);

        if (!skip) {
            unsigned bval = 0u, blo = 0u;
#pragma unroll
            for (int k = 0; k < PPT; k++) {
                float dx = __fsub_rn(px[k], cx);
                float dy = __fsub_rn(py[k], cy);
                float dz = __fsub_rn(pz[k], cz);
                float d  = __fadd_rn(__fadd_rn(__fmul_rn(dx, dx), __fmul_rn(dy, dy)),
                                     __fmul_rn(dz, dz));
                float nd = fminf(dmin[k], d);
                dmin[k]  = nd;
                unsigned vb = __float_as_uint(nd);
                unsigned lo = ~(unsigned)oidx[k];
                if (vb > bval || (vb == bval && lo > blo)) { bval = vb; blo = lo; }
            }
            warp_argmax2(bval, blo);
            if (lane == 0) {
                unsigned long long nk = ((unsigned long long)bval << 32) | blo;
                s_gkey[wid] = nk;
                s_wkey[wid] = nk;
            }
        }
        __syncthreads();

        if (wid == 0) {
            unsigned long long kk = (lane < FPS_WARPS) ? s_wkey[lane] : 0ull;
            unsigned v = (unsigned)(kk >> 32), lo = (unsigned)kk;
            warp_argmax2(v, lo);
            if (lane < FPS_CTAS) {
                unsigned long long key = ((unsigned long long)v << 32) | lo;
                uint32_t slot = sl0 + (uint32_t)(par * FPS_CTAS + rank) * 8u;
                st_cluster_u64(slot, (uint32_t)lane, key);
                mbar_arrive_cluster(mbar, (uint32_t)lane);
            }
        }

        mbar_wait_cluster(mbar, par);

        unsigned long long kk = s_slot[par][lane & 7];
        unsigned v = (unsigned)(kk >> 32), lo = (unsigned)kk;
        warp_argmax2(v, lo);          // duplicates are identical: max unaffected
        int winner = (int)(~lo);

        cx = sx[winner]; cy = sy[winner]; cz = sz[winner];
        if (rank == 0 && t == 0) g_idx[it] = winner;
        par ^= 1;
    }
}

// ---------------- ball query ------------------------------------------------

#define CAND_CAP 2048

__global__ void __launch_bounds__(256) ball_kernel(const float* __restrict__ pos)
{
    __shared__ unsigned long long keys[CAND_CAP];
    __shared__ int s_cnt;

    const int m   = blockIdx.x;
    const int tid = threadIdx.x;

    if (tid == 0) s_cnt = 0;
    __syncthreads();

    int ci = g_idx[m];
    float cx = pos[ci * 3 + 0];
    float cy = pos[ci * 3 + 1];
    float cz = pos[ci * 3 + 2];

    for (int j = tid; j < NPTS; j += 256) {
        float dx = cx - pos[j * 3 + 0];
        float dy = cy - pos[j * 3 + 1];
        float dz = cz - pos[j * 3 + 2];
        float d2 = __fadd_rn(__fadd_rn(__fmul_rn(dx, dx), __fmul_rn(dy, dy)),
                             __fmul_rn(dz, dz));
        if (d2 <= R2) {
            int p = atomicAdd(&s_cnt, 1);
            if (p < CAND_CAP) {
                unsigned long long k =
                    ((unsigned long long)__float_as_uint(d2) << 32) | (unsigned)j;
                keys[p] = k;
            }
        }
    }
    __syncthreads();

    int n = s_cnt;
    if (n > CAND_CAP) n = CAND_CAP;

    if (n > KNB) {
        int npow2 = 128;
        while (npow2 < n) npow2 <<= 1;
        for (int i = n + tid; i < npow2; i += 256)
            keys[i] = 0xFFFFFFFFFFFFFFFFull;
        __syncthreads();
        for (int k2 = 2; k2 <= npow2; k2 <<= 1) {
            for (int j2 = k2 >> 1; j2 > 0; j2 >>= 1) {
                for (int i = tid; i < npow2; i += 256) {
                    int l = i ^ j2;
                    if (l > i) {
                        unsigned long long a = keys[i], b = keys[l];
                        bool up = ((i & k2) == 0);
                        if ((a > b) == up) { keys[i] = b; keys[l] = a; }
                    }
                }
                __syncthreads();
            }
        }
    }

    int cnt = n < KNB ? n : KNB;
    if (tid < cnt)
        g_nbr[m * KNB + tid] = (int)(keys[tid] & 0xFFFFFFFFull);
    if (tid == 0) g_cnt[m] = cnt;
}

// ---------------- PointConv MLP + max-aggregate ------------------------------

#define W1SZ 4492
#define W2SZ 8576
#define VECSZ (3*67 + 3*128)
#define HROW 68
#define SMEM_FLOATS (W1SZ + W2SZ + VECSZ + 2*64*HROW)

__global__ void __launch_bounds__(128) mlp_kernel(
    const float* __restrict__ x,   const float* __restrict__ pos,
    const float* __restrict__ w1,  const float* __restrict__ b1,
    const float* __restrict__ g1,  const float* __restrict__ be1,
    const float* __restrict__ w2,  const float* __restrict__ b2,
    const float* __restrict__ g2,  const float* __restrict__ be2,
    float* __restrict__ out)
{
    extern __shared__ float sm[];
    float* sw1  = sm;
    float* sw2  = sw1 + W1SZ;
    float* sb1  = sw2 + W2SZ;
    float* sg1  = sb1 + 67;
    float* sbe1 = sg1 + 67;
    float* sb2  = sbe1 + 67;
    float* sg2  = sb2 + 128;
    float* sbe2 = sg2 + 128;
    float* sh0  = sbe2 + 128;
    float* sh1  = sh0 + 64 * HROW;

    __shared__ int   s_nbr[KNB];
    __shared__ float s_ps[3];
    __shared__ int   s_cnt;

    const int tid = threadIdx.x;
    const int m   = blockIdx.x;

    for (int i = tid; i < 4489; i += 128) sw1[i] = w1[i];
    for (int i = tid; i < W2SZ; i += 128) sw2[i] = w2[i];
    if (tid < 67)  { sb1[tid] = b1[tid]; sg1[tid] = g1[tid]; sbe1[tid] = be1[tid]; }
    if (tid < 128) { sb2[tid] = b2[tid]; sg2[tid] = g2[tid]; sbe2[tid] = be2[tid]; }
    if (tid == 0) {
        s_cnt = g_cnt[m];
        int ci = g_idx[m];
        s_ps[0] = pos[ci*3+0]; s_ps[1] = pos[ci*3+1]; s_ps[2] = pos[ci*3+2];
    }
    __syncthreads();

    const int cnt = s_cnt;
    if (tid < cnt) s_nbr[tid] = g_nbr[m * KNB + tid];
    __syncthreads();

    for (int e = tid; e < cnt * NIN; e += 128) {
        int r = e >> 6, c = e & 63;
        sh0[r * HROW + c] = x[s_nbr[r] * NIN + c];
    }
    for (int e = tid; e < cnt * 3; e += 128) {
        int r = e / 3, c = e - 3 * r;
        sh0[r * HROW + 64 + c] = pos[s_nbr[r] * 3 + c] - s_ps[c];
    }
    __syncthreads();

    const int r    = tid >> 1;
    const int half = tid & 1;
    const int c0   = half * 34;

    if (r < cnt) {
        float acc[34];
#pragma unroll
        for (int cc = 0; cc < 34; cc++) acc[cc] = 0.f;
        for (int i = 0; i < DIMF; i++) {
            float a = sh0[r * HROW + i];
            const float* wr = &sw1[i * 67 + c0];
#pragma unroll
            for (int cc = 0; cc < 34; cc++)
                if (c0 + cc < 67) acc[cc] = fmaf(a, wr[cc], acc[cc]);
        }
#pragma unroll
        for (int cc = 0; cc < 34; cc++) {
            int c = c0 + cc;
            if (c < 67) {
                float v = acc[cc] + sb1[c];
                v = fmaxf(v, 0.f);
                v = sg1[c] * (v * SFAC) + sbe1[c];
                sh1[r * HROW + c] = v;
            }
        }
    }
    __syncthreads();

    float acc2[64];
    if (r < cnt) {
#pragma unroll
        for (int cc = 0; cc < 64; cc++) acc2[cc] = 0.f;
        for (int i = 0; i < DIMF; i++) {
            float a = sh1[r * HROW + i];
            const float4* wr = reinterpret_cast<const float4*>(&sw2[i * 128 + half * 64]);
#pragma unroll
            for (int q = 0; q < 16; q++) {
                float4 w4 = wr[q];
                acc2[q*4+0] = fmaf(a, w4.x, acc2[q*4+0]);
                acc2[q*4+1] = fmaf(a, w4.y, acc2[q*4+1]);
                acc2[q*4+2] = fmaf(a, w4.z, acc2[q*4+2]);
                acc2[q*4+3] = fmaf(a, w4.w, acc2[q*4+3]);
            }
        }
    }
    __syncthreads();

    float* sred = sh0;
    if (r < cnt) {
#pragma unroll
        for (int cc = 0; cc < 64; cc++) {
            int c = half * 64 + cc;
            float v = acc2[cc] + sb2[c];
            v = fmaxf(v, 0.f);
            v = sg2[c] * (v * SFAC) + sbe2[c];
            sred[r * 128 + c] = v;
        }
    }
    __syncthreads();

    {
        int c = tid;
        float mv = sred[c];
        for (int rr = 1; rr < cnt; rr++)
            mv = fmaxf(mv, sred[rr * 128 + c]);
        out[m * NOUTF + c] = mv;
    }
}

// ---------------- epilogue ----------------------------------------------------
__global__ void __launch_bounds__(256) epi_kernel(
    const float* __restrict__ pos, const int* __restrict__ batch,
    float* __restrict__ out)
{
    int i = blockIdx.x * 256 + threadIdx.x;
    if (i < MCTR) {
        int j = g_idx[i];
        out[OFF_POS + i * 3 + 0] = pos[j * 3 + 0];
        out[OFF_POS + i * 3 + 1] = pos[j * 3 + 1];
        out[OFF_POS + i * 3 + 2] = pos[j * 3 + 2];
        out[OFF_BATCH + i] = (float)batch[j];
        out[OFF_IDX + i]   = (float)j;
    }
}

// ---------------- launch ------------------------------------------------------
extern "C" void kernel_launch(void* const* d_in, const int* in_sizes, int n_in,
                              void* d_out, int out_size)
{
    const float* x    = (const float*)d_in[0];
    const float* pos  = (const float*)d_in[1];
    const int*   batch= (const int*)  d_in[2];
    const float* w1   = (const float*)d_in[3];
    const float* b1   = (const float*)d_in[4];
    const float* g1   = (const float*)d_in[5];
    const float* be1  = (const float*)d_in[6];
    const float* w2   = (const float*)d_in[7];
    const float* b2   = (const float*)d_in[8];
    const float* g2   = (const float*)d_in[9];
    const float* be2  = (const float*)d_in[10];
    float* out = (float*)d_out;

    cudaFuncSetAttribute(sort_kernel, cudaFuncAttributeMaxDynamicSharedMemorySize,
                         NPTS * (int)sizeof(unsigned long long));
    cudaFuncSetAttribute(fps_cluster_kernel,
                         cudaFuncAttributeMaxDynamicSharedMemorySize,
                         3 * NPTS * (int)sizeof(float));
    cudaFuncSetAttribute(mlp_kernel, cudaFuncAttributeMaxDynamicSharedMemorySize,
                         SMEM_FLOATS * (int)sizeof(float));

    sort_kernel<<<1, 1024, NPTS * sizeof(unsigned long long)>>>(pos);
    fps_cluster_kernel<<<FPS_CTAS, FPS_THREADS, 3 * NPTS * sizeof(float)>>>(pos);
    ball_kernel<<<MCTR, 256>>>(pos);
    mlp_kernel<<<MCTR, 128, SMEM_FLOATS * sizeof(float)>>>(
        x, pos, w1, b1, g1, be1, w2, b2, g2, be2, out);
    epi_kernel<<<(MCTR + 255) / 256, 256>>>(pos, batch, out);
}